// round 10
// baseline (speedup 1.0000x reference)
#include <cuda_runtime.h>
#include <cuda_fp16.h>
#include <stdint.h>

// EdgeHead via warp-level mma.sync (HMMA fp16) + packed f32x2 scalar math +
// software-pipelined gathers (double-buffered raw registers, 2 CTAs/SM).
// out[e] = relu(LN([u,v,|u-v|,u*v]) @ (gamma.*W1) + bc) @ W2 + b2,
// bc = beta @ W1 + b1 (LN affine folded into weights).
// A fragments built in registers; LDG.128 gathers via k-axis permutation
// (B stored with the same permutation). Next group's 16 LDG.128 issue before
// current group's stats+MMA, hiding L2 gather latency behind ~5000 cyc of
// compute per group (ILP-hiding instead of TLP).

#define NTHREADS 128
typedef unsigned long long u64;

__device__ __forceinline__ u64 pk2(float x, float y) {
    u64 r; asm("mov.b64 %0, {%1, %2};" : "=l"(r) : "f"(x), "f"(y)); return r;
}
__device__ __forceinline__ void upk2(u64 a, float& x, float& y) {
    asm("mov.b64 {%0, %1}, %2;" : "=f"(x), "=f"(y) : "l"(a));
}
__device__ __forceinline__ u64 fma2(u64 a, u64 b, u64 c) {
    u64 r; asm("fma.rn.f32x2 %0, %1, %2, %3;" : "=l"(r) : "l"(a), "l"(b), "l"(c));
    return r;
}
__device__ __forceinline__ u64 add2(u64 a, u64 b) {
    u64 r; asm("add.rn.f32x2 %0, %1, %2;" : "=l"(r) : "l"(a), "l"(b)); return r;
}
__device__ __forceinline__ u64 mul2(u64 a, u64 b) {
    u64 r; asm("mul.rn.f32x2 %0, %1, %2;" : "=l"(r) : "l"(a), "l"(b)); return r;
}
#define ABS2MASK 0x7fffffff7fffffffULL

__device__ __forceinline__ uint32_t pack_h2(float x, float y) {
    __half2 t = __floats2half2_rn(x, y);   // .x = low half
    uint32_t r; memcpy(&r, &t, 4); return r;
}
__device__ __forceinline__ uint32_t h2_from2(u64 z) {
    float x, y; upk2(z, x, y); return pack_h2(x, y);
}

__device__ __forceinline__ void mma16816(float* c, const uint32_t* a,
                                         uint32_t b0, uint32_t b1) {
    asm volatile(
        "mma.sync.aligned.m16n8k16.row.col.f32.f16.f16.f32 "
        "{%0,%1,%2,%3}, {%4,%5,%6,%7}, {%8,%9}, {%0,%1,%2,%3};"
        : "+f"(c[0]), "+f"(c[1]), "+f"(c[2]), "+f"(c[3])
        : "r"(a[0]), "r"(a[1]), "r"(a[2]), "r"(a[3]), "r"(b0), "r"(b1));
}

__device__ __forceinline__ void ldsm4(uint32_t addr, uint32_t& r0, uint32_t& r1,
                                      uint32_t& r2, uint32_t& r3) {
    asm volatile("ldmatrix.sync.aligned.m8n8.x4.shared.b16 {%0,%1,%2,%3}, [%4];"
                 : "=r"(r0), "=r"(r1), "=r"(r2), "=r"(r3) : "r"(addr));
}

// packed z for feature segment s (compile-time): z = feat*rs + nm
__device__ __forceinline__ u64 zval2(int s, u64 uu, u64 vv, u64 rs2, u64 nm2,
                                     u64 neg1) {
    if (s == 0) return fma2(uu, rs2, nm2);
    if (s == 1) return fma2(vv, rs2, nm2);
    if (s == 2) {
        u64 d = fma2(vv, neg1, uu) & ABS2MASK;
        return fma2(d, rs2, nm2);
    }
    return fma2(mul2(uu, vv), rs2, nm2);
}

struct RawBuf {
    u64 U0[8], V0[8], U1[8], V1[8];   // 64 regs: f32x2 pairs for 2 edge rows
};

// issue the 16 LDG.128 for group g into r (indices clamped when invalid)
__device__ __forceinline__ void gather_group(
    RawBuf& r, int g, int E, bool wide,
    const int* __restrict__ ep32, const long long* __restrict__ ep64,
    const float4* __restrict__ hv4, int cq, int q)
{
    const int e0 = g * 16 + q;
    const int e1 = e0 + 8;
    const bool v0 = e0 < E, v1 = e1 < E;
    int s0, d0, s1i, d1;
    if (wide) {
        s0 = v0 ? (int)ep64[e0] : 0; d0 = v0 ? (int)ep64[e0 + E] : 0;
        s1i = v1 ? (int)ep64[e1] : 0; d1 = v1 ? (int)ep64[e1 + E] : 0;
    } else {
        s0 = v0 ? ep32[e0] : 0; d0 = v0 ? ep32[e0 + E] : 0;
        s1i = v1 ? ep32[e1] : 0; d1 = v1 ? ep32[e1 + E] : 0;
    }
    const float4* pu0 = hv4 + (s0 * 16 + cq);
    const float4* pv0 = hv4 + (d0 * 16 + cq);
    const float4* pu1 = hv4 + (s1i * 16 + cq);
    const float4* pv1 = hv4 + (d1 * 16 + cq);
    #pragma unroll
    for (int t = 0; t < 4; t++) {
        float4 a = pu0[4 * t];
        r.U0[2*t] = pk2(a.x, a.y); r.U0[2*t+1] = pk2(a.z, a.w);
        float4 b = pv0[4 * t];
        r.V0[2*t] = pk2(b.x, b.y); r.V0[2*t+1] = pk2(b.z, b.w);
        float4 c = pu1[4 * t];
        r.U1[2*t] = pk2(c.x, c.y); r.U1[2*t+1] = pk2(c.z, c.w);
        float4 d = pv1[4 * t];
        r.V1[2*t] = pk2(d.x, d.y); r.V1[2*t+1] = pk2(d.z, d.w);
    }
}

// stats + 16-kstep MMA + epilogue for group g using raw buffer r
__device__ __forceinline__ void process_group(
    const RawBuf& r, int g, int E, float* __restrict__ out,
    const float* __restrict__ bc_s, const float* __restrict__ w2_s,
    uint32_t bhiB, int x7, int pday, int cq, int q, float b2v, u64 neg1)
{
    // LN stats per row, packed (quad reduce after)
    u64 S1a = 0, S2a = 0, S1b = 0, S2b = 0;
    #pragma unroll
    for (int i = 0; i < 8; i++) {
        {
            const u64 uu = r.U0[i], vv = r.V0[i];
            const u64 p = mul2(uu, vv);
            const u64 d = fma2(vv, neg1, uu) & ABS2MASK;
            S1a = add2(S1a, add2(uu, vv));
            S1a = add2(S1a, add2(d, p));
            S2a = fma2(uu, uu, S2a); S2a = fma2(vv, vv, S2a);
            S2a = fma2(d, d, S2a);   S2a = fma2(p, p, S2a);
        }
        {
            const u64 uu = r.U1[i], vv = r.V1[i];
            const u64 p = mul2(uu, vv);
            const u64 d = fma2(vv, neg1, uu) & ABS2MASK;
            S1b = add2(S1b, add2(uu, vv));
            S1b = add2(S1b, add2(d, p));
            S2b = fma2(uu, uu, S2b); S2b = fma2(vv, vv, S2b);
            S2b = fma2(d, d, S2b);   S2b = fma2(p, p, S2b);
        }
    }
    float s1r0, s2r0, s1r1, s2r1, tx, ty;
    upk2(S1a, tx, ty); s1r0 = tx + ty;
    upk2(S2a, tx, ty); s2r0 = tx + ty;
    upk2(S1b, tx, ty); s1r1 = tx + ty;
    upk2(S2b, tx, ty); s2r1 = tx + ty;

    s1r0 += __shfl_xor_sync(0xffffffffu, s1r0, 1);
    s1r0 += __shfl_xor_sync(0xffffffffu, s1r0, 2);
    s2r0 += __shfl_xor_sync(0xffffffffu, s2r0, 1);
    s2r0 += __shfl_xor_sync(0xffffffffu, s2r0, 2);
    s1r1 += __shfl_xor_sync(0xffffffffu, s1r1, 1);
    s1r1 += __shfl_xor_sync(0xffffffffu, s1r1, 2);
    s2r1 += __shfl_xor_sync(0xffffffffu, s2r1, 1);
    s2r1 += __shfl_xor_sync(0xffffffffu, s2r1, 2);

    const float mu0 = s1r0 * (1.f / 256.f);
    const float rs0 = rsqrtf(fmaf(-mu0, mu0, s2r0 * (1.f / 256.f)) + 1e-5f);
    const float nm0 = -mu0 * rs0;
    const float mu1 = s1r1 * (1.f / 256.f);
    const float rs1 = rsqrtf(fmaf(-mu1, mu1, s2r1 * (1.f / 256.f)) + 1e-5f);
    const float nm1 = -mu1 * rs1;

    const u64 rs20 = pk2(rs0, rs0), nm20 = pk2(nm0, nm0);
    const u64 rs21 = pk2(rs1, rs1), nm21 = pk2(nm1, nm1);

    float acc[4][4];
    #pragma unroll
    for (int nt = 0; nt < 4; nt++)
        #pragma unroll
        for (int rr = 0; rr < 4; rr++) acc[nt][rr] = 0.f;

    // 16 ksteps: packed z -> A frags, ldmatrix B, 4 mma
    #pragma unroll
    for (int ks = 0; ks < 16; ks++) {
        const int s = ks >> 2, t = ks & 3;
        uint32_t ah[4];
        ah[0] = h2_from2(zval2(s, r.U0[2*t],   r.V0[2*t],   rs20, nm20, neg1));
        ah[1] = h2_from2(zval2(s, r.U1[2*t],   r.V1[2*t],   rs21, nm21, neg1));
        ah[2] = h2_from2(zval2(s, r.U0[2*t+1], r.V0[2*t+1], rs20, nm20, neg1));
        ah[3] = h2_from2(zval2(s, r.U1[2*t+1], r.V1[2*t+1], rs21, nm21, neg1));

        const uint32_t sw = (uint32_t)((((ks * 2 + pday) ^ x7)) << 4);
        uint32_t bh[8];
        ldsm4(bhiB + sw,        bh[0], bh[1], bh[2], bh[3]);   // nt 0,1
        ldsm4(bhiB + sw + 8192, bh[4], bh[5], bh[6], bh[7]);   // nt 2,3

        #pragma unroll
        for (int nt = 0; nt < 4; nt++)
            mma16816(acc[nt], ah, bh[2 * nt], bh[2 * nt + 1]);
    }

    // epilogue: relu + W2 dot (bc/w2 from smem), quad reduce
    const int c = cq * 2;
    float pp0 = 0.f, pp1 = 0.f;
    #pragma unroll
    for (int nt = 0; nt < 4; nt++) {
        const float bcx = bc_s[nt * 8 + c], bcy = bc_s[nt * 8 + c + 1];
        const float w2x = w2_s[nt * 8 + c], w2y = w2_s[nt * 8 + c + 1];
        pp0 = fmaf(fmaxf(acc[nt][0] + bcx, 0.f), w2x, pp0);
        pp0 = fmaf(fmaxf(acc[nt][1] + bcy, 0.f), w2y, pp0);
        pp1 = fmaf(fmaxf(acc[nt][2] + bcx, 0.f), w2x, pp1);
        pp1 = fmaf(fmaxf(acc[nt][3] + bcy, 0.f), w2y, pp1);
    }
    pp0 += __shfl_xor_sync(0xffffffffu, pp0, 1);
    pp0 += __shfl_xor_sync(0xffffffffu, pp0, 2);
    pp1 += __shfl_xor_sync(0xffffffffu, pp1, 1);
    pp1 += __shfl_xor_sync(0xffffffffu, pp1, 2);
    if (cq == 0) {
        const int e0 = g * 16 + q;
        const int e1 = e0 + 8;
        if (e0 < E) out[e0] = pp0 + b2v;
        if (e1 < E) out[e1] = pp1 + b2v;
    }
}

__global__ __launch_bounds__(NTHREADS, 2)
void edgehead_mma(const float* __restrict__ h,
                  const void* __restrict__ ep_raw,
                  const float* __restrict__ gamma,
                  const float* __restrict__ beta,
                  const float* __restrict__ W1,
                  const float* __restrict__ b1,
                  const float* __restrict__ W2,
                  const float* __restrict__ b2,
                  float* __restrict__ out,
                  int E, int nGroups)
{
    __shared__ __align__(128) unsigned char Bhi[16384];  // 32j x 256k fp16, swz
    __shared__ float bc_s[32], w2_s[32];

    const int tid = threadIdx.x;
    const int wid = tid >> 5;
    const int lane = tid & 31;

    // ---- stage B^T = (gamma .* W1)^T fp16, k-permuted + XOR-swizzled ----
    // phys k within 16-block maps to mma col m = ((k&12)>>1) + ((k&2)?8:0)
    for (int p = tid; p < 4096; p += NTHREADS) {
        const int j = p & 31;
        const int k0 = (p >> 5) << 1;                    // even phys k
        const float w0 = gamma[k0] * W1[k0 * 32 + j];
        const float w1 = gamma[k0 + 1] * W1[(k0 + 1) * 32 + j];
        const int m0 = ((k0 & 12) >> 1) + ((k0 & 2) ? 8 : 0);
        const int kp = (k0 & ~15) + m0;                  // permuted, even
        const uint32_t off = (uint32_t)(j * 512 + ((((kp >> 3)) ^ (j & 7)) << 4)
                                        + (kp & 7) * 2);
        *(uint32_t*)(Bhi + off) = pack_h2(w0, w1);
    }
    if (tid < 32) {
        float acc = b1[tid];
        #pragma unroll 8
        for (int k = 0; k < 256; k++) acc = fmaf(beta[k], W1[k * 32 + tid], acc);
        bc_s[tid] = acc;
        w2_s[tid] = W2[tid];
    }
    __syncthreads();

    // ---- edge index dtype sniff (int64 vs int32) ----
    const int* ep32 = (const int*)ep_raw;
    const long long* ep64 = (const long long*)ep_raw;
    int hiOr = 0;
    #pragma unroll
    for (int t = 1; t < 16; t += 2) hiOr |= ep32[t];
    const bool wide = (hiOr == 0);
    const float b2v = b2[0];
    const u64 neg1 = pk2(-1.f, -1.f);

    // ---- per-lane constants ----
    const int cq = lane & 3;           // quad position: owns phys dims 4cq..+3
    const int q = lane >> 2;           // edge row within group (and +8)
    const float4* __restrict__ hv4 = (const float4*)h;   // 16 float4 per node

    const int x7 = lane & 7;
    const int pday = (lane >> 3) & 1;
    const int jrow = ((lane >> 4)) * 8 + x7;
    const uint32_t bhiB = (uint32_t)__cvta_generic_to_shared(Bhi) + jrow * 512;

    const int gstride = gridDim.x * (NTHREADS / 32);
    int g = blockIdx.x * (NTHREADS / 32) + wid;
    if (g >= nGroups) return;

    // ---- software-pipelined main loop: prefetch next group's gathers ----
    RawBuf bufA, bufB;
    gather_group(bufA, g, E, wide, ep32, ep64, hv4, cq, q);

    for (;;) {
        // bufA current
        {
            const int gn = g + gstride;
            if (gn < nGroups)
                gather_group(bufB, gn, E, wide, ep32, ep64, hv4, cq, q);
            process_group(bufA, g, E, out, bc_s, w2_s, bhiB, x7, pday, cq, q,
                          b2v, neg1);
            if (gn >= nGroups) break;
            g = gn;
        }
        // bufB current
        {
            const int gn = g + gstride;
            if (gn < nGroups)
                gather_group(bufA, gn, E, wide, ep32, ep64, hv4, cq, q);
            process_group(bufB, g, E, out, bc_s, w2_s, bhiB, x7, pday, cq, q,
                          b2v, neg1);
            if (gn >= nGroups) break;
            g = gn;
        }
    }
}

extern "C" void kernel_launch(void* const* d_in, const int* in_sizes, int n_in,
                              void* d_out, int out_size)
{
    const float* h     = (const float*)d_in[0];
    const void*  ep    = d_in[1];
    const float* gamma = (const float*)d_in[2];
    const float* beta  = (const float*)d_in[3];
    const float* W1    = (const float*)d_in[4];
    const float* b1    = (const float*)d_in[5];
    const float* W2    = (const float*)d_in[6];
    const float* b2    = (const float*)d_in[7];
    float* out = (float*)d_out;
    const int E = out_size;
    const int nGroups = (E + 15) / 16;

    int dev = 0, sms = 148;
    cudaGetDevice(&dev);
    cudaDeviceGetAttribute(&sms, cudaDevAttrMultiProcessorCount, dev);
    int grid = sms * 2;
    const int maxg = (nGroups + (NTHREADS / 32) - 1) / (NTHREADS / 32);
    if (grid > maxg) grid = maxg;

    edgehead_mma<<<grid, NTHREADS>>>(h, ep, gamma, beta, W1, b1, W2, b2,
                                     out, E, nGroups);
}

// round 11
// speedup vs baseline: 1.0645x; 1.0645x over previous
#include <cuda_runtime.h>
#include <cuda_fp16.h>
#include <stdint.h>

// EdgeHead via warp-level mma.sync (HMMA fp16), R7 structure + fp16-compressed
// raw storage to reach 5 CTAs/SM (20 warps; R7 was reg-capped at 16).
// out[e] = relu(LN([u,v,|u-v|,u*v]) @ (gamma.*W1) + bc) @ W2 + b2,
// bc = beta @ W1 + b1 (LN affine folded into weights).
// Gathers LDG.128 via k-axis permutation (B stored with the same perm).
// LN stats computed inline at gather time from fp32 values (exact); raw u,v
// then kept as half2 (32 regs instead of 64). z built in fp32 from the
// half-rounded u,v (adds ~1 fp16 ulp to A; total err ~4.5e-4 < 1e-3).

#define NTHREADS 128
typedef unsigned long long u64;

__device__ __forceinline__ u64 pk2(float x, float y) {
    u64 r; asm("mov.b64 %0, {%1, %2};" : "=l"(r) : "f"(x), "f"(y)); return r;
}
__device__ __forceinline__ void upk2(u64 a, float& x, float& y) {
    asm("mov.b64 {%0, %1}, %2;" : "=f"(x), "=f"(y) : "l"(a));
}
__device__ __forceinline__ u64 fma2(u64 a, u64 b, u64 c) {
    u64 r; asm("fma.rn.f32x2 %0, %1, %2, %3;" : "=l"(r) : "l"(a), "l"(b), "l"(c));
    return r;
}
__device__ __forceinline__ u64 add2(u64 a, u64 b) {
    u64 r; asm("add.rn.f32x2 %0, %1, %2;" : "=l"(r) : "l"(a), "l"(b)); return r;
}
__device__ __forceinline__ u64 mul2(u64 a, u64 b) {
    u64 r; asm("mul.rn.f32x2 %0, %1, %2;" : "=l"(r) : "l"(a), "l"(b)); return r;
}
#define ABS2MASK 0x7fffffff7fffffffULL

__device__ __forceinline__ uint32_t pack_h2(float x, float y) {
    __half2 t = __floats2half2_rn(x, y);   // .x = low half
    uint32_t r; memcpy(&r, &t, 4); return r;
}

__device__ __forceinline__ void mma16816(float* c, const uint32_t* a,
                                         uint32_t b0, uint32_t b1) {
    asm volatile(
        "mma.sync.aligned.m16n8k16.row.col.f32.f16.f16.f32 "
        "{%0,%1,%2,%3}, {%4,%5,%6,%7}, {%8,%9}, {%0,%1,%2,%3};"
        : "+f"(c[0]), "+f"(c[1]), "+f"(c[2]), "+f"(c[3])
        : "r"(a[0]), "r"(a[1]), "r"(a[2]), "r"(a[3]), "r"(b0), "r"(b1));
}

__device__ __forceinline__ void ldsm4(uint32_t addr, uint32_t& r0, uint32_t& r1,
                                      uint32_t& r2, uint32_t& r3) {
    asm volatile("ldmatrix.sync.aligned.m8n8.x4.shared.b16 {%0,%1,%2,%3}, [%4];"
                 : "=r"(r0), "=r"(r1), "=r"(r2), "=r"(r3) : "r"(addr));
}

// stats accumulate for one packed (u,v) pair into S1,S2
__device__ __forceinline__ void statacc(u64 uu, u64 vv, u64 neg1,
                                        u64& S1, u64& S2) {
    const u64 p = mul2(uu, vv);
    const u64 d = fma2(vv, neg1, uu) & ABS2MASK;
    S1 = add2(S1, add2(uu, vv));
    S1 = add2(S1, add2(d, p));
    S2 = fma2(uu, uu, S2); S2 = fma2(vv, vv, S2);
    S2 = fma2(d, d, S2);   S2 = fma2(p, p, S2);
}

// z pair for feature segment s (compile-time), scalar fp32, packed to half2
__device__ __forceinline__ uint32_t zpack(int s, float2 u, float2 v,
                                          float rs, float nm) {
    float zx, zy;
    if (s == 0)      { zx = fmaf(u.x, rs, nm); zy = fmaf(u.y, rs, nm); }
    else if (s == 1) { zx = fmaf(v.x, rs, nm); zy = fmaf(v.y, rs, nm); }
    else if (s == 2) { zx = fmaf(fabsf(u.x - v.x), rs, nm);
                       zy = fmaf(fabsf(u.y - v.y), rs, nm); }
    else             { zx = fmaf(u.x * v.x, rs, nm);
                       zy = fmaf(u.y * v.y, rs, nm); }
    return pack_h2(zx, zy);
}

__device__ __forceinline__ float2 h2f2(uint32_t h) {
    return __half22float2(*reinterpret_cast<__half2*>(&h));
}

__global__ __launch_bounds__(NTHREADS, 5)
void edgehead_mma(const float* __restrict__ h,
                  const void* __restrict__ ep_raw,
                  const float* __restrict__ gamma,
                  const float* __restrict__ beta,
                  const float* __restrict__ W1,
                  const float* __restrict__ b1,
                  const float* __restrict__ W2,
                  const float* __restrict__ b2,
                  float* __restrict__ out,
                  int E, int nGroups)
{
    __shared__ __align__(128) unsigned char Bhi[16384];  // 32j x 256k fp16, swz
    __shared__ float bc_s[32], w2_s[32];

    const int tid = threadIdx.x;
    const int wid = tid >> 5;
    const int lane = tid & 31;

    // ---- stage B^T = (gamma .* W1)^T fp16, k-permuted + XOR-swizzled ----
    // phys k within 16-block maps to mma col m = ((k&12)>>1) + ((k&2)?8:0)
    for (int p = tid; p < 4096; p += NTHREADS) {
        const int j = p & 31;
        const int k0 = (p >> 5) << 1;                    // even phys k
        const float w0 = gamma[k0] * W1[k0 * 32 + j];
        const float w1 = gamma[k0 + 1] * W1[(k0 + 1) * 32 + j];
        const int m0 = ((k0 & 12) >> 1) + ((k0 & 2) ? 8 : 0);
        const int kp = (k0 & ~15) + m0;                  // permuted, even
        const uint32_t off = (uint32_t)(j * 512 + ((((kp >> 3)) ^ (j & 7)) << 4)
                                        + (kp & 7) * 2);
        *(uint32_t*)(Bhi + off) = pack_h2(w0, w1);
    }
    if (tid < 32) {
        float acc = b1[tid];
        #pragma unroll 8
        for (int k = 0; k < 256; k++) acc = fmaf(beta[k], W1[k * 32 + tid], acc);
        bc_s[tid] = acc;
        w2_s[tid] = W2[tid];
    }
    __syncthreads();

    // ---- edge index dtype sniff (int64 vs int32) ----
    const int* ep32 = (const int*)ep_raw;
    const long long* ep64 = (const long long*)ep_raw;
    int hiOr = 0;
    #pragma unroll
    for (int t = 1; t < 16; t += 2) hiOr |= ep32[t];
    const bool wide = (hiOr == 0);
    const float b2v = b2[0];
    const u64 neg1 = pk2(-1.f, -1.f);

    // ---- per-lane constants ----
    const int cq = lane & 3;           // quad position: owns phys dims 4cq..+3
    const int q = lane >> 2;           // edge row within group (and +8)
    const float4* __restrict__ hv4 = (const float4*)h;   // 16 float4 per node

    const int x7 = lane & 7;
    const int pday = (lane >> 3) & 1;
    const int jrow = ((lane >> 4)) * 8 + x7;
    const uint32_t bhiB = (uint32_t)__cvta_generic_to_shared(Bhi) + jrow * 512;

    const int gw = blockIdx.x * (NTHREADS / 32) + wid;
    const int gstride = gridDim.x * (NTHREADS / 32);

    for (int g = gw; g < nGroups; g += gstride) {
        const int e0 = g * 16 + q;
        const int e1 = e0 + 8;
        const bool v0 = e0 < E, v1 = e1 < E;
        int s0, d0, s1i, d1;
        if (wide) {
            s0 = v0 ? (int)ep64[e0] : 0; d0 = v0 ? (int)ep64[e0 + E] : 0;
            s1i = v1 ? (int)ep64[e1] : 0; d1 = v1 ? (int)ep64[e1 + E] : 0;
        } else {
            s0 = v0 ? ep32[e0] : 0; d0 = v0 ? ep32[e0 + E] : 0;
            s1i = v1 ? ep32[e1] : 0; d1 = v1 ? ep32[e1 + E] : 0;
        }

        // ---- gather + inline stats (fp32) + compress raws to half2 ----
        uint32_t Uh0[8], Vh0[8], Uh1[8], Vh1[8];   // 32 regs total
        u64 S1a = 0, S2a = 0, S1b = 0, S2b = 0;
        {
            const float4* pu0 = hv4 + (s0 * 16 + cq);
            const float4* pv0 = hv4 + (d0 * 16 + cq);
            const float4* pu1 = hv4 + (s1i * 16 + cq);
            const float4* pv1 = hv4 + (d1 * 16 + cq);
            #pragma unroll
            for (int t = 0; t < 4; t++) {
                const float4 a = pu0[4 * t];
                const float4 b = pv0[4 * t];
                const float4 c = pu1[4 * t];
                const float4 d = pv1[4 * t];
                statacc(pk2(a.x, a.y), pk2(b.x, b.y), neg1, S1a, S2a);
                statacc(pk2(a.z, a.w), pk2(b.z, b.w), neg1, S1a, S2a);
                statacc(pk2(c.x, c.y), pk2(d.x, d.y), neg1, S1b, S2b);
                statacc(pk2(c.z, c.w), pk2(d.z, d.w), neg1, S1b, S2b);
                Uh0[2*t] = pack_h2(a.x, a.y); Uh0[2*t+1] = pack_h2(a.z, a.w);
                Vh0[2*t] = pack_h2(b.x, b.y); Vh0[2*t+1] = pack_h2(b.z, b.w);
                Uh1[2*t] = pack_h2(c.x, c.y); Uh1[2*t+1] = pack_h2(c.z, c.w);
                Vh1[2*t] = pack_h2(d.x, d.y); Vh1[2*t+1] = pack_h2(d.z, d.w);
            }
        }
        float s1r0, s2r0, s1r1, s2r1, tx, ty;
        upk2(S1a, tx, ty); s1r0 = tx + ty;
        upk2(S2a, tx, ty); s2r0 = tx + ty;
        upk2(S1b, tx, ty); s1r1 = tx + ty;
        upk2(S2b, tx, ty); s2r1 = tx + ty;

        s1r0 += __shfl_xor_sync(0xffffffffu, s1r0, 1);
        s1r0 += __shfl_xor_sync(0xffffffffu, s1r0, 2);
        s2r0 += __shfl_xor_sync(0xffffffffu, s2r0, 1);
        s2r0 += __shfl_xor_sync(0xffffffffu, s2r0, 2);
        s1r1 += __shfl_xor_sync(0xffffffffu, s1r1, 1);
        s1r1 += __shfl_xor_sync(0xffffffffu, s1r1, 2);
        s2r1 += __shfl_xor_sync(0xffffffffu, s2r1, 1);
        s2r1 += __shfl_xor_sync(0xffffffffu, s2r1, 2);

        const float mu0 = s1r0 * (1.f / 256.f);
        const float rs0 = rsqrtf(fmaf(-mu0, mu0, s2r0 * (1.f / 256.f)) + 1e-5f);
        const float nm0 = -mu0 * rs0;
        const float mu1 = s1r1 * (1.f / 256.f);
        const float rs1 = rsqrtf(fmaf(-mu1, mu1, s2r1 * (1.f / 256.f)) + 1e-5f);
        const float nm1 = -mu1 * rs1;

        float acc[4][4];
        #pragma unroll
        for (int nt = 0; nt < 4; nt++)
            #pragma unroll
            for (int rr = 0; rr < 4; rr++) acc[nt][rr] = 0.f;

        // ---- mma loop: t outer (unpack once), s inner; ks = 4s + t ----
        #pragma unroll
        for (int t = 0; t < 4; t++) {
            const float2 u0l = h2f2(Uh0[2*t]), u0h = h2f2(Uh0[2*t+1]);
            const float2 v0l = h2f2(Vh0[2*t]), v0h = h2f2(Vh0[2*t+1]);
            const float2 u1l = h2f2(Uh1[2*t]), u1h = h2f2(Uh1[2*t+1]);
            const float2 v1l = h2f2(Vh1[2*t]), v1h = h2f2(Vh1[2*t+1]);
            #pragma unroll
            for (int s = 0; s < 4; s++) {
                const int ks = s * 4 + t;
                uint32_t ah[4];
                ah[0] = zpack(s, u0l, v0l, rs0, nm0);   // row q,   k-lo
                ah[1] = zpack(s, u1l, v1l, rs1, nm1);   // row q+8, k-lo
                ah[2] = zpack(s, u0h, v0h, rs0, nm0);   // row q,   k-hi
                ah[3] = zpack(s, u1h, v1h, rs1, nm1);   // row q+8, k-hi

                const uint32_t sw = (uint32_t)((((ks * 2 + pday) ^ x7)) << 4);
                uint32_t bh[8];
                ldsm4(bhiB + sw,        bh[0], bh[1], bh[2], bh[3]);   // nt 0,1
                ldsm4(bhiB + sw + 8192, bh[4], bh[5], bh[6], bh[7]);   // nt 2,3

                #pragma unroll
                for (int nt = 0; nt < 4; nt++)
                    mma16816(acc[nt], ah, bh[2 * nt], bh[2 * nt + 1]);
            }
        }

        // ---- epilogue: relu + W2 dot (bc/w2 from smem), quad reduce ----
        const int c = cq * 2;
        float pp0 = 0.f, pp1 = 0.f;
        #pragma unroll
        for (int nt = 0; nt < 4; nt++) {
            const float bcx = bc_s[nt * 8 + c], bcy = bc_s[nt * 8 + c + 1];
            const float w2x = w2_s[nt * 8 + c], w2y = w2_s[nt * 8 + c + 1];
            pp0 = fmaf(fmaxf(acc[nt][0] + bcx, 0.f), w2x, pp0);
            pp0 = fmaf(fmaxf(acc[nt][1] + bcy, 0.f), w2y, pp0);
            pp1 = fmaf(fmaxf(acc[nt][2] + bcx, 0.f), w2x, pp1);
            pp1 = fmaf(fmaxf(acc[nt][3] + bcy, 0.f), w2y, pp1);
        }
        pp0 += __shfl_xor_sync(0xffffffffu, pp0, 1);
        pp0 += __shfl_xor_sync(0xffffffffu, pp0, 2);
        pp1 += __shfl_xor_sync(0xffffffffu, pp1, 1);
        pp1 += __shfl_xor_sync(0xffffffffu, pp1, 2);
        if (cq == 0) {
            if (v0) out[e0] = pp0 + b2v;
            if (v1) out[e1] = pp1 + b2v;
        }
    }
}

extern "C" void kernel_launch(void* const* d_in, const int* in_sizes, int n_in,
                              void* d_out, int out_size)
{
    const float* h     = (const float*)d_in[0];
    const void*  ep    = d_in[1];
    const float* gamma = (const float*)d_in[2];
    const float* beta  = (const float*)d_in[3];
    const float* W1    = (const float*)d_in[4];
    const float* b1    = (const float*)d_in[5];
    const float* W2    = (const float*)d_in[6];
    const float* b2    = (const float*)d_in[7];
    float* out = (float*)d_out;
    const int E = out_size;
    const int nGroups = (E + 15) / 16;

    int dev = 0, sms = 148;
    cudaGetDevice(&dev);
    cudaDeviceGetAttribute(&sms, cudaDevAttrMultiProcessorCount, dev);
    int grid = sms * 5;
    const int maxg = (nGroups + (NTHREADS / 32) - 1) / (NTHREADS / 32);
    if (grid > maxg) grid = maxg;

    edgehead_mma<<<grid, NTHREADS>>>(h, ep, gamma, beta, W1, b1, W2, b2,
                                     out, E, nGroups);
}